// round 6
// baseline (speedup 1.0000x reference)
#include <cuda_runtime.h>
#include <cuda_fp16.h>

// ---------------------------------------------------------------------------
// f16-accumulate MMA + movmatrix wrappers (sm_75+/sm_80, fine on compute_103)
// ---------------------------------------------------------------------------
__device__ __forceinline__ void mmaf16_16816(unsigned* d, const unsigned* a,
                                             unsigned b0, unsigned b1,
                                             unsigned c0, unsigned c1) {
    asm volatile(
        "mma.sync.aligned.m16n8k16.row.col.f16.f16.f16.f16 "
        "{%0,%1}, {%2,%3,%4,%5}, {%6,%7}, {%8,%9};"
        : "=r"(d[0]), "=r"(d[1])
        : "r"(a[0]), "r"(a[1]), "r"(a[2]), "r"(a[3]),
          "r"(b0), "r"(b1), "r"(c0), "r"(c1));
}
__device__ __forceinline__ void mmaf16_1688(unsigned* d, const unsigned* a,
                                            unsigned b0,
                                            unsigned c0, unsigned c1) {
    asm volatile(
        "mma.sync.aligned.m16n8k8.row.col.f16.f16.f16.f16 "
        "{%0,%1}, {%2,%3}, {%4}, {%5,%6};"
        : "=r"(d[0]), "=r"(d[1])
        : "r"(a[0]), "r"(a[1]), "r"(b0), "r"(c0), "r"(c1));
}
__device__ __forceinline__ unsigned movmt(unsigned a) {
    unsigned d;
    asm("movmatrix.sync.aligned.m8n8.trans.b16 %0, %1;" : "=r"(d) : "r"(a));
    return d;
}
__device__ __forceinline__ __half2 tanh2(__half2 x) {
    unsigned xi = *reinterpret_cast<unsigned*>(&x), yi;
    asm("tanh.approx.f16x2 %0, %1;" : "=r"(yi) : "r"(xi));
    return *reinterpret_cast<__half2*>(&yi);
}
__device__ __forceinline__ __half2 sig2(__half2 x) {
    const __half2 h05 = __float2half2_rn(0.5f);
    return __hfma2(tanh2(__hmul2(x, h05)), h05, h05);
}
__device__ __forceinline__ unsigned pack2(float lo, float hi) {
    __half2 h = __floats2half2_rn(lo, hi);
    return *reinterpret_cast<unsigned*>(&h);
}
__device__ __forceinline__ __half2 u2h(unsigned u) {
    return *reinterpret_cast<__half2*>(&u);
}

// ---------------------------------------------------------------------------
// Warp-autonomous fused LSTM, full-f16 datapath, TWO independent 8-row
// groups per warp (16 batch rows/warp). The two groups share the register-
// resident weights and have no data dependence -> per-warp ILP hides the
// MMA->MUFU->movmatrix serial chain that bound previous rounds.
// ---------------------------------------------------------------------------
__global__ void __launch_bounds__(64, 4) lstm_fused(
    const float* __restrict__ x,
    const int* __restrict__ mat_idx, const int* __restrict__ freq_idx,
    const float* __restrict__ W_ih, const float* __restrict__ W_hh,
    const float* __restrict__ b_ih, const float* __restrict__ b_hh,
    const float* __restrict__ mat_emb, const float* __restrict__ freq_emb,
    const float* __restrict__ fc_w, const float* __restrict__ fc_b,
    float* __restrict__ out, int T)
{
    const int tid  = threadIdx.x;
    const int wid  = tid >> 5, lane = tid & 31;
    const int q    = lane & 3;            // batch col-pair selector
    const int gid  = lane >> 2;           // row-in-tile

    // warp owns rows [warpbase, warpbase+16); group g: +8*g
    const long long warpbase = ((long long)blockIdx.x * 2 + wid) * 16;

    // ---- stationary A fragments (weights), shared by both groups ----
    auto wval = [&](int n, int k) -> float {
        if (k < 32)  return W_hh[n * 32 + k];
        if (k < 35)  return W_ih[n * 3 + (k - 32)];
        if (k == 35) return b_ih[n] + b_hh[n];
        return 0.f;
    };
    unsigned af[8][2][4];   // m-tile, k16-chunk, frag
    unsigned af2[8][2];     // k8 chunk (x + bias)
#pragma unroll
    for (int mt = 0; mt < 8; ++mt) {
        int n0 = 16 * mt + gid, n1 = n0 + 8;
#pragma unroll
        for (int kc = 0; kc < 2; ++kc) {
            int k0 = 16 * kc + 2 * q;
            af[mt][kc][0] = pack2(wval(n0, k0),     wval(n0, k0 + 1));
            af[mt][kc][1] = pack2(wval(n1, k0),     wval(n1, k0 + 1));
            af[mt][kc][2] = pack2(wval(n0, k0 + 8), wval(n0, k0 + 9));
            af[mt][kc][3] = pack2(wval(n1, k0 + 8), wval(n1, k0 + 9));
        }
        int k2 = 32 + 2 * q;
        af2[mt][0] = pack2(wval(n0, k2), wval(n0, k2 + 1));
        af2[mt][1] = pack2(wval(n1, k2), wval(n1, k2 + 1));
    }

    // ---- per-group x streams (lanes q=0/1 carry data) ----
    const float* pxr[2];
    float xp0[2], xp1[2], xp2[2];
#pragma unroll
    for (int g = 0; g < 2; ++g) {
        pxr[g] = x + (size_t)(warpbase + 8 * g + gid) * T * 3;
        xp0[g] = xp1[g] = xp2[g] = 0.f;
        if (q == 0) { xp0[g] = pxr[g][0]; xp1[g] = pxr[g][1]; }
        else if (q == 1) { xp2[g] = pxr[g][2]; }
    }

    // ---- loop-carried state, per group ----
    unsigned b00[2] = {0,0}, b01[2] = {0,0}, b10[2] = {0,0}, b11[2] = {0,0};
    __half2 cst[2][4];
#pragma unroll
    for (int g = 0; g < 2; ++g)
#pragma unroll
        for (int s = 0; s < 4; ++s) cst[g][s] = __float2half2_rn(0.f);
    unsigned hs[2][4];

    for (int t = 0; t < T; ++t) {
        // B chunk-2 fragments (x + 1) and next-x prefetch, both groups
        unsigned b2[2];
#pragma unroll
        for (int g = 0; g < 2; ++g) {
            if (q == 0)      b2[g] = pack2(xp0[g], xp1[g]);
            else if (q == 1) b2[g] = pack2(xp2[g], 1.f);
            else             b2[g] = 0u;
        }
        if (t + 1 < T) {
#pragma unroll
            for (int g = 0; g < 2; ++g) {
                const float* p = pxr[g] + (size_t)(t + 1) * 3;
                if (q == 0) { xp0[g] = p[0]; xp1[g] = p[1]; }
                else if (q == 1) { xp2[g] = p[2]; }
            }
        }

        // ---- 48 tensor ops (24 per group), groups interleaved by ptxas ----
        unsigned acc[2][8][2];
#pragma unroll
        for (int g = 0; g < 2; ++g) {
#pragma unroll
            for (int mt = 0; mt < 8; ++mt)
                mmaf16_16816(acc[g][mt], af[mt][0], b00[g], b01[g], 0u, 0u);
#pragma unroll
            for (int mt = 0; mt < 8; ++mt)
                mmaf16_16816(acc[g][mt], af[mt][1], b10[g], b11[g],
                             acc[g][mt][0], acc[g][mt][1]);
#pragma unroll
            for (int mt = 0; mt < 8; ++mt)
                mmaf16_1688(acc[g][mt], af2[mt], b2[g],
                            acc[g][mt][0], acc[g][mt][1]);
        }

        // ---- LSTM updates; epilogue of g=0 overlaps MMA latency of g=1 ----
#pragma unroll
        for (int g = 0; g < 2; ++g) {
#pragma unroll
            for (int half = 0; half < 2; ++half) {
#pragma unroll
                for (int rsel = 0; rsel < 2; ++rsel) {
                    int s = half * 2 + rsel;
                    __half2 si = sig2(u2h(acc[g][0 + half][rsel]));
                    __half2 sf = sig2(u2h(acc[g][2 + half][rsel]));
                    __half2 tg = tanh2(u2h(acc[g][4 + half][rsel]));
                    __half2 so = sig2(u2h(acc[g][6 + half][rsel]));
                    __half2 cc = __hfma2(sf, cst[g][s], __hmul2(si, tg));
                    cst[g][s] = cc;
                    __half2 hv = __hmul2(so, tanh2(cc));
                    hs[g][s] = *reinterpret_cast<unsigned*>(&hv);
                }
            }
            b00[g] = movmt(hs[g][0]);   // units 0-7
            b01[g] = movmt(hs[g][1]);   // units 8-15
            b10[g] = movmt(hs[g][2]);   // units 16-23
            b11[g] = movmt(hs[g][3]);   // units 24-31
        }
    }

    // ---- fc head: out[r] = h_T . fc_w[0:32] + emb + fc_b ----
#pragma unroll
    for (int g = 0; g < 2; ++g) {
        float p_lo = 0.f, p_hi = 0.f;   // batch rows base+2q, base+2q+1
#pragma unroll
        for (int s = 0; s < 4; ++s) {
            __half2 hv = u2h(hs[g][s]);
            float w = fc_w[8 * s + gid];
            p_lo = fmaf(__low2float(hv),  w, p_lo);
            p_hi = fmaf(__high2float(hv), w, p_hi);
        }
#pragma unroll
        for (int off = 4; off < 32; off <<= 1) {
            p_lo += __shfl_xor_sync(0xFFFFFFFFu, p_lo, off);
            p_hi += __shfl_xor_sync(0xFFFFFFFFu, p_hi, off);
        }
        if (lane < 4) {
            float base = fc_b[0];
#pragma unroll
            for (int k = 0; k < 2; ++k) {
                long long r = warpbase + 8 * g + 2 * q + k;
                float s = (k ? p_hi : p_lo) + base;
                int mi = mat_idx[r], fi = freq_idx[r];
#pragma unroll
                for (int e = 0; e < 4; ++e)
                    s += mat_emb[mi * 4 + e] * fc_w[32 + e];
#pragma unroll
                for (int e = 0; e < 2; ++e)
                    s += freq_emb[fi * 2 + e] * fc_w[36 + e];
                out[r] = s;
            }
        }
    }
}

extern "C" void kernel_launch(void* const* d_in, const int* in_sizes, int n_in,
                              void* d_out, int out_size) {
    const float* x        = (const float*)d_in[0];
    const int*   mat_idx  = (const int*)  d_in[1];
    const int*   freq_idx = (const int*)  d_in[2];
    const float* W_ih     = (const float*)d_in[3];
    const float* W_hh     = (const float*)d_in[4];
    const float* b_ih     = (const float*)d_in[5];
    const float* b_hh     = (const float*)d_in[6];
    const float* mat_emb  = (const float*)d_in[7];
    const float* freq_emb = (const float*)d_in[8];
    const float* fc_w     = (const float*)d_in[9];
    const float* fc_b     = (const float*)d_in[10];

    int B = in_sizes[1];                  // mat_idx has B elements
    int T = in_sizes[0] / (B * 3);        // x has B*T*3 elements
    int grid = B / 32;                    // 32 rows/CTA (2 warps x 16 rows)

    lstm_fused<<<grid, 64>>>(x, mat_idx, freq_idx, W_ih, W_hh, b_ih, b_hh,
                             mat_emb, freq_emb, fc_w, fc_b,
                             (float*)d_out, T);
}

// round 7
// speedup vs baseline: 1.4755x; 1.4755x over previous
#include <cuda_runtime.h>
#include <cuda_fp16.h>

// ---------------------------------------------------------------------------
// f16-accumulate MMA + movmatrix wrappers (sm_75+/sm_80, fine on compute_103)
// ---------------------------------------------------------------------------
__device__ __forceinline__ void mmaf16_16816(unsigned* d, const unsigned* a,
                                             unsigned b0, unsigned b1,
                                             unsigned c0, unsigned c1) {
    asm volatile(
        "mma.sync.aligned.m16n8k16.row.col.f16.f16.f16.f16 "
        "{%0,%1}, {%2,%3,%4,%5}, {%6,%7}, {%8,%9};"
        : "=r"(d[0]), "=r"(d[1])
        : "r"(a[0]), "r"(a[1]), "r"(a[2]), "r"(a[3]),
          "r"(b0), "r"(b1), "r"(c0), "r"(c1));
}
__device__ __forceinline__ void mmaf16_1688(unsigned* d, const unsigned* a,
                                            unsigned b0,
                                            unsigned c0, unsigned c1) {
    asm volatile(
        "mma.sync.aligned.m16n8k8.row.col.f16.f16.f16.f16 "
        "{%0,%1}, {%2,%3}, {%4}, {%5,%6};"
        : "=r"(d[0]), "=r"(d[1])
        : "r"(a[0]), "r"(a[1]), "r"(b0), "r"(c0), "r"(c1));
}
__device__ __forceinline__ unsigned movmt(unsigned a) {
    unsigned d;
    asm("movmatrix.sync.aligned.m8n8.trans.b16 %0, %1;" : "=r"(d) : "r"(a));
    return d;
}
__device__ __forceinline__ __half2 tanh2(__half2 x) {
    unsigned xi = *reinterpret_cast<unsigned*>(&x), yi;
    asm("tanh.approx.f16x2 %0, %1;" : "=r"(yi) : "r"(xi));
    return *reinterpret_cast<__half2*>(&yi);
}
__device__ __forceinline__ __half2 sig2(__half2 x) {
    const __half2 h05 = __float2half2_rn(0.5f);
    return __hfma2(tanh2(__hmul2(x, h05)), h05, h05);
}
__device__ __forceinline__ unsigned pack2(float lo, float hi) {
    __half2 h = __floats2half2_rn(lo, hi);
    return *reinterpret_cast<unsigned*>(&h);
}
__device__ __forceinline__ __half2 u2h(unsigned u) {
    return *reinterpret_cast<__half2*>(&u);
}

// ---------------------------------------------------------------------------
// Gate-split fused LSTM: a 2-warp CTA owns 8 batch rows.
// Warp p computes ALL 4 gates of hidden units [16p, 16p+16):
//   D[64 x 8] = A[64 x 48](weights, regs) * B[48 x 8](state)  -> 12 MMA/warp
// Epilogue stays thread-local (each warp has i,f,g,o of its own units).
// h exchange: movmatrix -> STS.64 -> syncthreads -> 2x LDS.64 (parity-
// double-buffered SMEM, one barrier per step).
// 2048 CTAs x 2 warps = 4096 warps -> 28/SM (one full wave at 72 regs).
// ---------------------------------------------------------------------------
__global__ void __launch_bounds__(64, 14) lstm_fused(
    const float* __restrict__ x,
    const int* __restrict__ mat_idx, const int* __restrict__ freq_idx,
    const float* __restrict__ W_ih, const float* __restrict__ W_hh,
    const float* __restrict__ b_ih, const float* __restrict__ b_hh,
    const float* __restrict__ mat_emb, const float* __restrict__ freq_emb,
    const float* __restrict__ fc_w, const float* __restrict__ fc_b,
    float* __restrict__ out, int T)
{
    __shared__ unsigned long long sx[2][2][32];   // [buf][warp][lane] h-frags
    __shared__ float sred[2][4][2];               // fc partials [warp][q][lo/hi]

    const int tid  = threadIdx.x;
    const int wid  = tid >> 5, lane = tid & 31;
    const int q    = lane & 3;            // batch col-pair selector
    const int gid  = lane >> 2;           // row-in-tile

    const long long rowbase = (long long)blockIdx.x * 8;

    // ---- stationary A fragments: warp wid owns units [16*wid, 16*wid+16) ----
    auto wval = [&](int n, int k) -> float {
        if (k < 32)  return W_hh[n * 32 + k];
        if (k < 35)  return W_ih[n * 3 + (k - 32)];
        if (k == 35) return b_ih[n] + b_hh[n];
        return 0.f;
    };
    unsigned af[4][2][4];   // gate, k16-chunk, frag
    unsigned af2[4][2];     // k8 chunk (x + bias)
#pragma unroll
    for (int g = 0; g < 4; ++g) {
        int n0 = g * 32 + 16 * wid + gid, n1 = n0 + 8;
#pragma unroll
        for (int kc = 0; kc < 2; ++kc) {
            int k0 = 16 * kc + 2 * q;
            af[g][kc][0] = pack2(wval(n0, k0),     wval(n0, k0 + 1));
            af[g][kc][1] = pack2(wval(n1, k0),     wval(n1, k0 + 1));
            af[g][kc][2] = pack2(wval(n0, k0 + 8), wval(n0, k0 + 9));
            af[g][kc][3] = pack2(wval(n1, k0 + 8), wval(n1, k0 + 9));
        }
        int k2 = 32 + 2 * q;
        af2[g][0] = pack2(wval(n0, k2), wval(n0, k2 + 1));
        af2[g][1] = pack2(wval(n1, k2), wval(n1, k2 + 1));
    }

    // ---- x stream for batch row rowbase+gid (lanes q=0/1 carry data) ----
    const float* pxr = x + (size_t)(rowbase + gid) * T * 3;
    float xp0 = 0.f, xp1 = 0.f, xp2 = 0.f;
    if (q == 0) { xp0 = pxr[0]; xp1 = pxr[1]; }
    else if (q == 1) { xp2 = pxr[2]; }

    // ---- loop-carried state ----
    unsigned b00 = 0, b01 = 0, b10 = 0, b11 = 0;   // full h fragments (t=0: 0)
    __half2 cst[2];
    cst[0] = __float2half2_rn(0.f);
    cst[1] = __float2half2_rn(0.f);
    unsigned hs[2];
    hs[0] = hs[1] = 0u;

    for (int t = 0; t < T; ++t) {
        unsigned b2;
        if (q == 0)      b2 = pack2(xp0, xp1);
        else if (q == 1) b2 = pack2(xp2, 1.f);
        else             b2 = 0u;

        if (t + 1 < T) {   // prefetch next x under the MMAs
            const float* p = pxr + (size_t)(t + 1) * 3;
            if (q == 0) { xp0 = p[0]; xp1 = p[1]; }
            else if (q == 1) { xp2 = p[2]; }
        }

        // ---- 12 MMAs: x-projection (h-independent) first, then h chunks ----
        unsigned acc[4][2];
#pragma unroll
        for (int g = 0; g < 4; ++g)
            mmaf16_1688(acc[g], af2[g], b2, 0u, 0u);
#pragma unroll
        for (int g = 0; g < 4; ++g)
            mmaf16_16816(acc[g], af[g][0], b00, b01, acc[g][0], acc[g][1]);
#pragma unroll
        for (int g = 0; g < 4; ++g)
            mmaf16_16816(acc[g], af[g][1], b10, b11, acc[g][0], acc[g][1]);

        // ---- LSTM update: slot s -> unit 16*wid + 8*s + gid, batch {2q,2q+1}
#pragma unroll
        for (int s = 0; s < 2; ++s) {
            __half2 si = sig2(u2h(acc[0][s]));
            __half2 sf = sig2(u2h(acc[1][s]));
            __half2 tg = tanh2(u2h(acc[2][s]));
            __half2 so = sig2(u2h(acc[3][s]));
            __half2 cc = __hfma2(sf, cst[s], __hmul2(si, tg));
            cst[s] = cc;
            __half2 hv = __hmul2(so, tanh2(cc));
            hs[s] = *reinterpret_cast<unsigned*>(&hv);
        }

        // ---- exchange h fragments with partner warp ----
        unsigned f0 = movmt(hs[0]);        // k-rows 16*wid   .. +8
        unsigned f1 = movmt(hs[1]);        // k-rows 16*wid+8 .. +16
        const int buf = t & 1;
        sx[buf][wid][lane] =
            (unsigned long long)f0 | ((unsigned long long)f1 << 32);
        __syncthreads();
        unsigned long long w0 = sx[buf][0][lane];
        unsigned long long w1 = sx[buf][1][lane];
        b00 = (unsigned)w0; b01 = (unsigned)(w0 >> 32);
        b10 = (unsigned)w1; b11 = (unsigned)(w1 >> 32);
    }

    // ---- fc head: partial over this warp's 16 units, then pair-reduce ----
    float p_lo = 0.f, p_hi = 0.f;          // batch rows rowbase+2q, +2q+1
#pragma unroll
    for (int s = 0; s < 2; ++s) {
        __half2 hv = u2h(hs[s]);
        float w = fc_w[16 * wid + 8 * s + gid];
        p_lo = fmaf(__low2float(hv),  w, p_lo);
        p_hi = fmaf(__high2float(hv), w, p_hi);
    }
#pragma unroll
    for (int off = 4; off < 32; off <<= 1) {
        p_lo += __shfl_xor_sync(0xFFFFFFFFu, p_lo, off);
        p_hi += __shfl_xor_sync(0xFFFFFFFFu, p_hi, off);
    }
    if (lane < 4) { sred[wid][q][0] = p_lo; sred[wid][q][1] = p_hi; }
    __syncthreads();
    if (tid < 4) {
        float base = fc_b[0];
#pragma unroll
        for (int k = 0; k < 2; ++k) {
            long long r = rowbase + 2 * tid + k;
            float s = sred[0][tid][k] + sred[1][tid][k] + base;
            int mi = mat_idx[r], fi = freq_idx[r];
#pragma unroll
            for (int e = 0; e < 4; ++e) s += mat_emb[mi * 4 + e] * fc_w[32 + e];
#pragma unroll
            for (int e = 0; e < 2; ++e) s += freq_emb[fi * 2 + e] * fc_w[36 + e];
            out[r] = s;
        }
    }
}

extern "C" void kernel_launch(void* const* d_in, const int* in_sizes, int n_in,
                              void* d_out, int out_size) {
    const float* x        = (const float*)d_in[0];
    const int*   mat_idx  = (const int*)  d_in[1];
    const int*   freq_idx = (const int*)  d_in[2];
    const float* W_ih     = (const float*)d_in[3];
    const float* W_hh     = (const float*)d_in[4];
    const float* b_ih     = (const float*)d_in[5];
    const float* b_hh     = (const float*)d_in[6];
    const float* mat_emb  = (const float*)d_in[7];
    const float* freq_emb = (const float*)d_in[8];
    const float* fc_w     = (const float*)d_in[9];
    const float* fc_b     = (const float*)d_in[10];

    int B = in_sizes[1];                  // mat_idx has B elements
    int T = in_sizes[0] / (B * 3);        // x has B*T*3 elements
    int grid = B / 8;                     // 8 rows per 2-warp CTA

    lstm_fused<<<grid, 64>>>(x, mat_idx, freq_idx, W_ih, W_hh, b_ih, b_hh,
                             mat_emb, freq_emb, fc_w, fc_b,
                             (float*)d_out, T);
}